// round 1
// baseline (speedup 1.0000x reference)
#include <cuda_runtime.h>

#define Bsz 16
#define Npt 4096
#define Kn  20
#define NROW (Bsz*Npt*Kn)      // 1,310,720 rows
#define HID 64
#define NEG_SLOPE 0.2f
#define EPSBN 1e-5f

// ---------------- scratch (device globals; no runtime allocation) ----------------
__device__ int   g_idx[Bsz*Npt*Kn];                 // kNN indices (local to batch)
__device__ float g_A  [Bsz*Npt*HID];                // x . W1a^T  (gathered by neighbor)
__device__ float g_Bv [Bsz*Npt*HID];                // x . (W1b-W1a)^T (per center point)
__device__ float g_z2 [(size_t)NROW*HID];           // lrelu(layer2) rows
__device__ float g_z3 [(size_t)NROW*HID];           // lrelu(layer3) rows
__device__ float g_sum[3][HID];
__device__ float g_sq [3][HID];
__device__ float g_scale[3][HID];
__device__ float g_shift[3][HID];

__device__ __forceinline__ float lrelu(float v){ return v > 0.f ? v : NEG_SLOPE*v; }

// ---------------- init: zero stat accumulators (graph replay safe) ----------------
__global__ void zero_stats_kernel(){
    int t = threadIdx.x;
    if (t < 3*HID){ ((float*)g_sum)[t] = 0.f; ((float*)g_sq)[t] = 0.f; }
}

// ---------------- per-point precompute for linearized layer 1 ----------------
// f = [nbr-x, x]; y1 = f @ W1^T = nbr.W1a^T + x.(W1b-W1a)^T  => A[nbr] + Bv[n]
__global__ void point_feats_kernel(const float* __restrict__ x, const float* __restrict__ W1){
    int p = blockIdx.x;            // global point 0..65535
    int o = threadIdx.x;           // channel 0..63
    int b = p >> 12, n = p & (Npt-1);
    const float* xb = x + (size_t)b*3*Npt;
    float x0 = __ldg(xb + n), x1 = __ldg(xb + Npt + n), x2 = __ldg(xb + 2*Npt + n);
    float w0 = W1[o*6+0], w1 = W1[o*6+1], w2 = W1[o*6+2];
    float w3 = W1[o*6+3], w4 = W1[o*6+4], w5 = W1[o*6+5];
    g_A [p*HID+o] = x0*w0 + x1*w1 + x2*w2;
    g_Bv[p*HID+o] = x0*(w3-w0) + x1*(w4-w1) + x2*(w5-w2);
}

// ---------------- brute-force exact kNN (top-20 of neg squared distance) ----------------
#define KNN_TQ   128
#define KNN_TILE 1024
__global__ void knn_kernel(const float* __restrict__ x){
    __shared__ float4 tile[KNN_TILE];
    int b = blockIdx.y;
    int i = blockIdx.x*KNN_TQ + threadIdx.x;
    const float* xb = x + (size_t)b*3*Npt;
    float xi0 = xb[i], xi1 = xb[Npt+i], xi2 = xb[2*Npt+i];
    float sqi = xi0*xi0 + xi1*xi1 + xi2*xi2;

    const float NEG_INF = -__int_as_float(0x7f800000);
    float vals[Kn]; int inds[Kn];
    #pragma unroll
    for (int t = 0; t < Kn; t++){ vals[t] = NEG_INF; inds[t] = 0; }
    float thr = NEG_INF;

    for (int t0 = 0; t0 < Npt; t0 += KNN_TILE){
        __syncthreads();
        for (int j = threadIdx.x; j < KNN_TILE; j += KNN_TQ){
            float px = xb[t0+j], py = xb[Npt+t0+j], pz = xb[2*Npt+t0+j];
            tile[j] = make_float4(px, py, pz, px*px + py*py + pz*pz);
        }
        __syncthreads();
        #pragma unroll 4
        for (int j = 0; j < KNN_TILE; j++){
            float4 p = tile[j];
            float dot = xi0*p.x + xi1*p.y + xi2*p.z;
            float v = 2.f*dot - sqi - p.w;           // matches reference formula
            if (v > thr){                             // strict: ties keep earlier index
                int pos = Kn-1;
                while (pos > 0 && vals[pos-1] < v){
                    vals[pos] = vals[pos-1]; inds[pos] = inds[pos-1]; pos--;
                }
                vals[pos] = v; inds[pos] = t0 + j;
                thr = vals[Kn-1];
            }
        }
    }
    int base = (b*Npt + i)*Kn;
    #pragma unroll
    for (int t = 0; t < Kn; t++) g_idx[base+t] = inds[t];
}

// ---------------- stats of z1 = lrelu(A[nbr]+Bv[n]) (z1 never materialized) ----------------
__global__ void stats1_kernel(){
    int tid = blockIdx.x*blockDim.x + threadIdx.x;
    int cg  = (tid & 7)*8;                       // 8-channel group
    int rl  = tid >> 3;
    int nrl = (gridDim.x*blockDim.x) >> 3;
    float s[8], q[8];
    #pragma unroll
    for (int u = 0; u < 8; u++){ s[u] = 0.f; q[u] = 0.f; }

    for (int row = rl; row < NROW; row += nrl){
        int pnt = row / Kn;                      // b*N + n
        int b = pnt >> 12;
        int nbr = g_idx[row];
        const float4* Ap = (const float4*)(g_A  + (size_t)((b<<12)+nbr)*HID + cg);
        const float4* Bp = (const float4*)(g_Bv + (size_t)pnt*HID + cg);
        float4 a0 = Ap[0], a1 = Ap[1], v0 = Bp[0], v1 = Bp[1];
        float z;
        z = lrelu(a0.x+v0.x); s[0]+=z; q[0]+=z*z;
        z = lrelu(a0.y+v0.y); s[1]+=z; q[1]+=z*z;
        z = lrelu(a0.z+v0.z); s[2]+=z; q[2]+=z*z;
        z = lrelu(a0.w+v0.w); s[3]+=z; q[3]+=z*z;
        z = lrelu(a1.x+v1.x); s[4]+=z; q[4]+=z*z;
        z = lrelu(a1.y+v1.y); s[5]+=z; q[5]+=z*z;
        z = lrelu(a1.z+v1.z); s[6]+=z; q[6]+=z*z;
        z = lrelu(a1.w+v1.w); s[7]+=z; q[7]+=z*z;
    }
    __shared__ float shs[HID], shq[HID];
    if (threadIdx.x < HID){ shs[threadIdx.x] = 0.f; shq[threadIdx.x] = 0.f; }
    __syncthreads();
    #pragma unroll
    for (int u = 0; u < 8; u++){ atomicAdd(&shs[cg+u], s[u]); atomicAdd(&shq[cg+u], q[u]); }
    __syncthreads();
    if (threadIdx.x < HID){
        atomicAdd(&g_sum[0][threadIdx.x], shs[threadIdx.x]);
        atomicAdd(&g_sq [0][threadIdx.x], shq[threadIdx.x]);
    }
}

// ---------------- BN affine finalize: z -> z*scale + shift ----------------
__global__ void finalize_kernel(int l, const float* __restrict__ gam, const float* __restrict__ bet){
    int c = threadIdx.x;
    float inv = 1.f/(float)NROW;
    float mu  = g_sum[l][c]*inv;
    float var = g_sq[l][c]*inv - mu*mu;
    float sc  = gam[c]*rsqrtf(var + EPSBN);
    g_scale[l][c] = sc;
    g_shift[l][c] = bet[c] - mu*sc;
}

// ---------------- fused normalize + 64x64 GEMM + lrelu + store + stats ----------------
// MODE 0: input = recomputed z1 (gather A/Bv), weights W2, writes g_z2, stats slot 1
// MODE 1: input = g_z2,                          weights W3, writes g_z3, stats slot 2
template<int MODE>
__global__ void __launch_bounds__(256) layer_kernel(const float* __restrict__ W){
    __shared__ __align__(16) float ws [HID][HID];   // ws[c][o] = W[o][c]
    __shared__ __align__(16) float ins[HID][128];   // ins[c][row_local] (normalized input)
    int tid = threadIdx.x;
    int row0 = blockIdx.x * 128;

    for (int t = tid; t < HID*HID; t += 256)
        ws[t & 63][t >> 6] = W[t];

    {   // load + normalize 128 rows x 64 ch; 2 threads/row (32-channel halves)
        int lr = tid >> 1, h = (tid & 1)*32;
        int row = row0 + lr;
        if (MODE == 0){
            int pnt = row / Kn;
            int b = pnt >> 12;
            int nbr = g_idx[row];
            const float4* P0 = (const float4*)(g_A  + (size_t)((b<<12)+nbr)*HID + h);
            const float4* P1 = (const float4*)(g_Bv + (size_t)pnt*HID + h);
            #pragma unroll
            for (int u = 0; u < 8; u++){
                float4 a = P0[u], v = P1[u];
                int c = h + u*4;
                ins[c+0][lr] = lrelu(a.x+v.x)*g_scale[0][c+0] + g_shift[0][c+0];
                ins[c+1][lr] = lrelu(a.y+v.y)*g_scale[0][c+1] + g_shift[0][c+1];
                ins[c+2][lr] = lrelu(a.z+v.z)*g_scale[0][c+2] + g_shift[0][c+2];
                ins[c+3][lr] = lrelu(a.w+v.w)*g_scale[0][c+3] + g_shift[0][c+3];
            }
        } else {
            const float4* Z = (const float4*)(g_z2 + (size_t)row*HID + h);
            #pragma unroll
            for (int u = 0; u < 8; u++){
                float4 zz = Z[u];
                int c = h + u*4;
                ins[c+0][lr] = zz.x*g_scale[1][c+0] + g_shift[1][c+0];
                ins[c+1][lr] = zz.y*g_scale[1][c+1] + g_shift[1][c+1];
                ins[c+2][lr] = zz.z*g_scale[1][c+2] + g_shift[1][c+2];
                ins[c+3][lr] = zz.w*g_scale[1][c+3] + g_shift[1][c+3];
            }
        }
    }
    __syncthreads();

    int tr = tid >> 4;           // 16 row groups of 8
    int tc = (tid & 15)*4;       // 16 col groups of 4
    float acc[8][4];
    #pragma unroll
    for (int r = 0; r < 8; r++)
        #pragma unroll
        for (int j = 0; j < 4; j++) acc[r][j] = 0.f;

    #pragma unroll 8
    for (int c = 0; c < HID; c++){
        float4 w4 = *(const float4*)&ws[c][tc];
        float4 i0 = *(const float4*)&ins[c][tr*8];
        float4 i1 = *(const float4*)&ins[c][tr*8+4];
        float in[8] = {i0.x,i0.y,i0.z,i0.w,i1.x,i1.y,i1.z,i1.w};
        float wv[4] = {w4.x,w4.y,w4.z,w4.w};
        #pragma unroll
        for (int r = 0; r < 8; r++)
            #pragma unroll
            for (int j = 0; j < 4; j++)
                acc[r][j] += in[r]*wv[j];
    }
    __syncthreads();

    // reuse ins smem for block stat reduction
    float* shs = &ins[0][0];
    float* shq = shs + HID;
    if (tid < 2*HID) shs[tid] = 0.f;
    __syncthreads();

    float* OUTP = (MODE == 0) ? g_z2 : g_z3;
    float ls[4] = {0,0,0,0}, lq[4] = {0,0,0,0};
    #pragma unroll
    for (int r = 0; r < 8; r++){
        int grow = row0 + tr*8 + r;
        float z0 = lrelu(acc[r][0]);
        float z1 = lrelu(acc[r][1]);
        float z2 = lrelu(acc[r][2]);
        float z3 = lrelu(acc[r][3]);
        *(float4*)(OUTP + (size_t)grow*HID + tc) = make_float4(z0,z1,z2,z3);
        ls[0]+=z0; lq[0]+=z0*z0;
        ls[1]+=z1; lq[1]+=z1*z1;
        ls[2]+=z2; lq[2]+=z2*z2;
        ls[3]+=z3; lq[3]+=z3*z3;
    }
    #pragma unroll
    for (int j = 0; j < 4; j++){
        atomicAdd(&shs[tc+j], ls[j]);
        atomicAdd(&shq[tc+j], lq[j]);
    }
    __syncthreads();
    if (tid < HID){
        atomicAdd(&g_sum[MODE+1][tid], shs[tid]);
        atomicAdd(&g_sq [MODE+1][tid], shq[tid]);
    }
}

// ---------------- max over k, then BN affine (monotone, gamma>0), transpose to [B,64,N] ----------------
__global__ void final_kernel(float* __restrict__ out){
    __shared__ float sh[HID][65];
    int pt0 = blockIdx.x * 64;                     // 64 points per block
    int o = threadIdx.x & 63;
    float sc = g_scale[2][o], tt = g_shift[2][o];
    const float NEG_INF = -__int_as_float(0x7f800000);
    for (int nl = threadIdx.x >> 6; nl < 64; nl += 4){
        const float* zr = g_z3 + (size_t)(pt0+nl)*Kn*HID + o;
        float m = NEG_INF;
        #pragma unroll
        for (int kk = 0; kk < Kn; kk++) m = fmaxf(m, zr[kk*HID]);
        sh[o][nl] = m*sc + tt;
    }
    __syncthreads();
    int b = pt0 >> 12, n0 = pt0 & (Npt-1);
    int n = threadIdx.x & 63;
    for (int ol = threadIdx.x >> 6; ol < 64; ol += 4)
        out[((size_t)b*HID + ol)*Npt + n0 + n] = sh[ol][n];
}

// ---------------- launch ----------------
extern "C" void kernel_launch(void* const* d_in, const int* in_sizes, int n_in,
                              void* d_out, int out_size){
    const float* x  = (const float*)d_in[0];
    const float* W1 = (const float*)d_in[1];
    const float* W2 = (const float*)d_in[2];
    const float* W3 = (const float*)d_in[3];
    const float* g1 = (const float*)d_in[4];
    const float* b1 = (const float*)d_in[5];
    const float* g2 = (const float*)d_in[6];
    const float* b2 = (const float*)d_in[7];
    float* out = (float*)d_out;

    zero_stats_kernel<<<1, 3*HID>>>();
    point_feats_kernel<<<Bsz*Npt, HID>>>(x, W1);
    dim3 kg(Npt/KNN_TQ, Bsz);
    knn_kernel<<<kg, KNN_TQ>>>(x);
    stats1_kernel<<<4096, 256>>>();
    finalize_kernel<<<1, HID>>>(0, g1, b1);
    layer_kernel<0><<<NROW/128, 256>>>(W2);
    finalize_kernel<<<1, HID>>>(1, g1, b1);
    layer_kernel<1><<<NROW/128, 256>>>(W3);
    finalize_kernel<<<1, HID>>>(2, g2, b2);
    final_kernel<<<Bsz*Npt/64, 256>>>(out);
}

// round 2
// speedup vs baseline: 4.7200x; 4.7200x over previous
#include <cuda_runtime.h>

#define Bsz 16
#define Npt 4096
#define Kn  20
#define NROW (Bsz*Npt*Kn)      // 1,310,720 rows
#define HID 64
#define NEG_SLOPE 0.2f
#define EPSBN 1e-5f

// ---------------- scratch (device globals; no runtime allocation) ----------------
__device__ int   g_idx[Bsz*Npt*Kn];                 // kNN index sets (local to batch)
__device__ float g_A  [Bsz*Npt*HID];                // x . W1a^T  (gathered by neighbor)
__device__ float g_Bv [Bsz*Npt*HID];                // x . (W1b-W1a)^T (per center point)
__device__ float g_z2 [(size_t)NROW*HID];           // lrelu(layer2) rows
__device__ float g_z3 [(size_t)NROW*HID];           // lrelu(layer3) rows
__device__ float g_sum[3][HID];
__device__ float g_sq [3][HID];
__device__ float g_scale[3][HID];
__device__ float g_shift[3][HID];

__device__ __forceinline__ float lrelu(float v){ return v > 0.f ? v : NEG_SLOPE*v; }

// packed f32x2 helpers (sm_100+)
#define FMA2(d,a,b,c) asm("fma.rn.f32x2 %0, %1, %2, %3;" : "=l"(d) : "l"(a), "l"(b), "l"(c))
__device__ __forceinline__ unsigned long long packff(float lo, float hi){
    unsigned long long r;
    asm("mov.b64 %0, {%1, %2};" : "=l"(r) : "r"(__float_as_uint(lo)), "r"(__float_as_uint(hi)));
    return r;
}
__device__ __forceinline__ void unpackff(unsigned long long a, float& lo, float& hi){
    unsigned ulo, uhi;
    asm("mov.b64 {%0, %1}, %2;" : "=r"(ulo), "=r"(uhi) : "l"(a));
    lo = __uint_as_float(ulo); hi = __uint_as_float(uhi);
}

// ---------------- init: zero stat accumulators (graph replay safe) ----------------
__global__ void zero_stats_kernel(){
    int t = threadIdx.x;
    if (t < 3*HID){ ((float*)g_sum)[t] = 0.f; ((float*)g_sq)[t] = 0.f; }
}

// ---------------- per-point precompute for linearized layer 1 ----------------
// f = [nbr-x, x]; y1 = f @ W1^T = nbr.W1a^T + x.(W1b-W1a)^T  => A[nbr] + Bv[n]
__global__ void point_feats_kernel(const float* __restrict__ x, const float* __restrict__ W1){
    int p = blockIdx.x;            // global point 0..65535
    int o = threadIdx.x;           // channel 0..63
    int b = p >> 12, n = p & (Npt-1);
    const float* xb = x + (size_t)b*3*Npt;
    float x0 = __ldg(xb + n), x1 = __ldg(xb + Npt + n), x2 = __ldg(xb + 2*Npt + n);
    float w0 = W1[o*6+0], w1 = W1[o*6+1], w2 = W1[o*6+2];
    float w3 = W1[o*6+3], w4 = W1[o*6+4], w5 = W1[o*6+5];
    g_A [p*HID+o] = x0*w0 + x1*w1 + x2*w2;
    g_Bv[p*HID+o] = x0*(w3-w0) + x1*(w4-w1) + x2*(w5-w2);
}

// ---------------- exact kNN, two-phase threshold select, pure registers ----------------
// Phase 1: top-20 VALUES via branch-guarded, fully-unrolled FMNMX bubble network.
// Phase 2: emit index set {v > T} plus first-e ties (v == T), e = multiplicity of T
//          in the top-20 multiset. Downstream is permutation-invariant over k.
#define KNN_TQ   128
#define KNN_TILE 1024

__device__ __forceinline__ float pair_v(float xi0,float xi1,float xi2,float sqi,float4 p){
    float dot = __fmaf_rn(xi2, p.z, __fmaf_rn(xi1, p.y, __fmul_rn(xi0, p.x)));
    return __fsub_rn(__fsub_rn(__fmul_rn(2.f, dot), sqi), p.w);
}

__global__ void __launch_bounds__(KNN_TQ) knn_kernel(const float* __restrict__ x){
    __shared__ float4 tile[KNN_TILE];
    int b = blockIdx.y;
    int i = blockIdx.x*KNN_TQ + threadIdx.x;
    const float* xb = x + (size_t)b*3*Npt;
    float xi0 = xb[i], xi1 = xb[Npt+i], xi2 = xb[2*Npt+i];
    float sqi = __fmaf_rn(xi2, xi2, __fmaf_rn(xi1, xi1, __fmul_rn(xi0, xi0)));

    const float NEG_INF = -__int_as_float(0x7f800000);
    float kv[Kn];                                  // ascending; kv[0] = 20th largest
    #pragma unroll
    for (int t = 0; t < Kn; t++) kv[t] = NEG_INF;

    // ---- phase 1: values ----
    for (int t0 = 0; t0 < Npt; t0 += KNN_TILE){
        __syncthreads();
        for (int j = threadIdx.x; j < KNN_TILE; j += KNN_TQ){
            float px = xb[t0+j], py = xb[Npt+t0+j], pz = xb[2*Npt+t0+j];
            tile[j] = make_float4(px, py, pz,
                __fmaf_rn(pz, pz, __fmaf_rn(py, py, __fmul_rn(px, px))));
        }
        __syncthreads();
        #pragma unroll 2
        for (int j = 0; j < KNN_TILE; j++){
            float v = pair_v(xi0, xi1, xi2, sqi, tile[j]);
            if (v > kv[0]){
                float c = v;                        // bubble into ascending array
                #pragma unroll
                for (int t = 0; t < Kn-1; t++){
                    float lo = fminf(kv[t+1], c);
                    float hi = fmaxf(kv[t+1], c);
                    kv[t] = lo; c = hi;
                }
                kv[Kn-1] = c;
            }
        }
    }

    float T = kv[0];
    int e = 0;
    #pragma unroll
    for (int t = 0; t < Kn; t++) e += (kv[t] == T) ? 1 : 0;

    // ---- phase 2: indices ----
    int base = (b*Npt + i)*Kn;
    int cnt = 0;
    for (int t0 = 0; t0 < Npt; t0 += KNN_TILE){
        __syncthreads();
        for (int j = threadIdx.x; j < KNN_TILE; j += KNN_TQ){
            float px = xb[t0+j], py = xb[Npt+t0+j], pz = xb[2*Npt+t0+j];
            tile[j] = make_float4(px, py, pz,
                __fmaf_rn(pz, pz, __fmaf_rn(py, py, __fmul_rn(px, px))));
        }
        __syncthreads();
        #pragma unroll 2
        for (int j = 0; j < KNN_TILE; j++){
            float v = pair_v(xi0, xi1, xi2, sqi, tile[j]);
            if (v >= T && cnt < Kn){
                if (v > T){
                    g_idx[base + cnt++] = t0 + j;
                } else if (e > 0){                 // tie at threshold: lowest indices win
                    g_idx[base + cnt++] = t0 + j;
                    e--;
                }
            }
        }
    }
    for (; cnt < Kn; cnt++) g_idx[base + cnt] = i;  // safety (unreachable)
}

// ---------------- stats of z1 = lrelu(A[nbr]+Bv[n]) (z1 never materialized) ----------------
__global__ void stats1_kernel(){
    int tid = blockIdx.x*blockDim.x + threadIdx.x;
    int cg  = (tid & 7)*8;                       // 8-channel group
    int rl  = tid >> 3;
    int nrl = (gridDim.x*blockDim.x) >> 3;
    float s[8], q[8];
    #pragma unroll
    for (int u = 0; u < 8; u++){ s[u] = 0.f; q[u] = 0.f; }

    for (int row = rl; row < NROW; row += nrl){
        int pnt = row / Kn;                      // b*N + n
        int b = pnt >> 12;
        int nbr = g_idx[row];
        const float4* Ap = (const float4*)(g_A  + (size_t)((b<<12)+nbr)*HID + cg);
        const float4* Bp = (const float4*)(g_Bv + (size_t)pnt*HID + cg);
        float4 a0 = Ap[0], a1 = Ap[1], v0 = Bp[0], v1 = Bp[1];
        float z;
        z = lrelu(a0.x+v0.x); s[0]+=z; q[0]+=z*z;
        z = lrelu(a0.y+v0.y); s[1]+=z; q[1]+=z*z;
        z = lrelu(a0.z+v0.z); s[2]+=z; q[2]+=z*z;
        z = lrelu(a0.w+v0.w); s[3]+=z; q[3]+=z*z;
        z = lrelu(a1.x+v1.x); s[4]+=z; q[4]+=z*z;
        z = lrelu(a1.y+v1.y); s[5]+=z; q[5]+=z*z;
        z = lrelu(a1.z+v1.z); s[6]+=z; q[6]+=z*z;
        z = lrelu(a1.w+v1.w); s[7]+=z; q[7]+=z*z;
    }
    __shared__ float shs[HID], shq[HID];
    if (threadIdx.x < HID){ shs[threadIdx.x] = 0.f; shq[threadIdx.x] = 0.f; }
    __syncthreads();
    #pragma unroll
    for (int u = 0; u < 8; u++){ atomicAdd(&shs[cg+u], s[u]); atomicAdd(&shq[cg+u], q[u]); }
    __syncthreads();
    if (threadIdx.x < HID){
        atomicAdd(&g_sum[0][threadIdx.x], shs[threadIdx.x]);
        atomicAdd(&g_sq [0][threadIdx.x], shq[threadIdx.x]);
    }
}

// ---------------- BN affine finalize: z -> z*scale + shift ----------------
__global__ void finalize_kernel(int l, const float* __restrict__ gam, const float* __restrict__ bet){
    int c = threadIdx.x;
    float inv = 1.f/(float)NROW;
    float mu  = g_sum[l][c]*inv;
    float var = g_sq[l][c]*inv - mu*mu;
    float sc  = gam[c]*rsqrtf(var + EPSBN);
    g_scale[l][c] = sc;
    g_shift[l][c] = bet[c] - mu*sc;
}

// ---------------- fused normalize + 64x64 GEMM (f32x2) + lrelu + store + stats ----------------
// MODE 0: input = recomputed z1 (gather A/Bv), weights W2, writes g_z2, stats slot 1
// MODE 1: input = g_z2,                          weights W3, writes g_z3, stats slot 2
template<int MODE>
__global__ void __launch_bounds__(256) layer_kernel(const float* __restrict__ W){
    __shared__ __align__(16) float ws [HID][HID];   // ws[c][o] = W[o][c]
    __shared__ __align__(16) float ins[HID][128];   // ins[c][row_local] (normalized input)
    int tid = threadIdx.x;
    int row0 = blockIdx.x * 128;

    for (int t = tid; t < HID*HID; t += 256)
        ws[t & 63][t >> 6] = W[t];

    {   // load + normalize 128 rows x 64 ch; 2 threads/row (32-channel halves)
        int lr = tid >> 1, h = (tid & 1)*32;
        int row = row0 + lr;
        if (MODE == 0){
            int pnt = row / Kn;
            int b = pnt >> 12;
            int nbr = g_idx[row];
            const float4* P0 = (const float4*)(g_A  + (size_t)((b<<12)+nbr)*HID + h);
            const float4* P1 = (const float4*)(g_Bv + (size_t)pnt*HID + h);
            #pragma unroll
            for (int u = 0; u < 8; u++){
                float4 a = P0[u], v = P1[u];
                int c = h + u*4;
                ins[c+0][lr] = lrelu(a.x+v.x)*g_scale[0][c+0] + g_shift[0][c+0];
                ins[c+1][lr] = lrelu(a.y+v.y)*g_scale[0][c+1] + g_shift[0][c+1];
                ins[c+2][lr] = lrelu(a.z+v.z)*g_scale[0][c+2] + g_shift[0][c+2];
                ins[c+3][lr] = lrelu(a.w+v.w)*g_scale[0][c+3] + g_shift[0][c+3];
            }
        } else {
            const float4* Z = (const float4*)(g_z2 + (size_t)row*HID + h);
            #pragma unroll
            for (int u = 0; u < 8; u++){
                float4 zz = Z[u];
                int c = h + u*4;
                ins[c+0][lr] = zz.x*g_scale[1][c+0] + g_shift[1][c+0];
                ins[c+1][lr] = zz.y*g_scale[1][c+1] + g_shift[1][c+1];
                ins[c+2][lr] = zz.z*g_scale[1][c+2] + g_shift[1][c+2];
                ins[c+3][lr] = zz.w*g_scale[1][c+3] + g_shift[1][c+3];
            }
        }
    }
    __syncthreads();

    int tr = tid >> 4;           // 16 row groups of 8
    int tc = (tid & 15)*4;       // 16 col groups of 4

    // acc[rp][j]: packed pair (row tr*8+2rp, row tr*8+2rp+1) at column tc+j
    unsigned long long acc[4][4];
    #pragma unroll
    for (int rp = 0; rp < 4; rp++)
        #pragma unroll
        for (int j = 0; j < 4; j++) acc[rp][j] = 0ULL;   // (0.f, 0.f)

    #pragma unroll 8
    for (int c = 0; c < HID; c++){
        float4 w4 = *(const float4*)&ws[c][tc];
        ulonglong2 I0 = *(const ulonglong2*)&ins[c][tr*8];
        ulonglong2 I1 = *(const ulonglong2*)&ins[c][tr*8+4];
        unsigned long long inp[4] = {I0.x, I0.y, I1.x, I1.y};
        unsigned long long ww [4] = {packff(w4.x,w4.x), packff(w4.y,w4.y),
                                     packff(w4.z,w4.z), packff(w4.w,w4.w)};
        #pragma unroll
        for (int rp = 0; rp < 4; rp++)
            #pragma unroll
            for (int j = 0; j < 4; j++)
                FMA2(acc[rp][j], inp[rp], ww[j], acc[rp][j]);
    }
    __syncthreads();

    // reuse ins smem for block stat reduction
    float* shs = &ins[0][0];
    float* shq = shs + HID;
    if (tid < 2*HID) shs[tid] = 0.f;
    __syncthreads();

    float* OUTP = (MODE == 0) ? g_z2 : g_z3;
    float ls[4] = {0,0,0,0}, lq[4] = {0,0,0,0};
    #pragma unroll
    for (int rp = 0; rp < 4; rp++){
        float zlo[4], zhi[4];
        #pragma unroll
        for (int j = 0; j < 4; j++){
            float lo, hi; unpackff(acc[rp][j], lo, hi);
            zlo[j] = lrelu(lo); zhi[j] = lrelu(hi);
            ls[j] += zlo[j] + zhi[j];
            lq[j] += zlo[j]*zlo[j] + zhi[j]*zhi[j];
        }
        int rlo = row0 + tr*8 + 2*rp;
        *(float4*)(OUTP + (size_t)rlo*HID + tc)     = make_float4(zlo[0],zlo[1],zlo[2],zlo[3]);
        *(float4*)(OUTP + (size_t)(rlo+1)*HID + tc) = make_float4(zhi[0],zhi[1],zhi[2],zhi[3]);
    }
    #pragma unroll
    for (int j = 0; j < 4; j++){
        atomicAdd(&shs[tc+j], ls[j]);
        atomicAdd(&shq[tc+j], lq[j]);
    }
    __syncthreads();
    if (tid < HID){
        atomicAdd(&g_sum[MODE+1][tid], shs[tid]);
        atomicAdd(&g_sq [MODE+1][tid], shq[tid]);
    }
}

// ---------------- max over k, then BN affine (monotone, gamma>0), transpose to [B,64,N] ----------------
__global__ void final_kernel(float* __restrict__ out){
    __shared__ float sh[HID][65];
    int pt0 = blockIdx.x * 64;                     // 64 points per block
    int o = threadIdx.x & 63;
    float sc = g_scale[2][o], tt = g_shift[2][o];
    const float NEG_INF = -__int_as_float(0x7f800000);
    for (int nl = threadIdx.x >> 6; nl < 64; nl += 4){
        const float* zr = g_z3 + (size_t)(pt0+nl)*Kn*HID + o;
        float m = NEG_INF;
        #pragma unroll
        for (int kk = 0; kk < Kn; kk++) m = fmaxf(m, zr[kk*HID]);
        sh[o][nl] = m*sc + tt;
    }
    __syncthreads();
    int b = pt0 >> 12, n0 = pt0 & (Npt-1);
    int n = threadIdx.x & 63;
    for (int ol = threadIdx.x >> 6; ol < 64; ol += 4)
        out[((size_t)b*HID + ol)*Npt + n0 + n] = sh[ol][n];
}

// ---------------- launch ----------------
extern "C" void kernel_launch(void* const* d_in, const int* in_sizes, int n_in,
                              void* d_out, int out_size){
    const float* x  = (const float*)d_in[0];
    const float* W1 = (const float*)d_in[1];
    const float* W2 = (const float*)d_in[2];
    const float* W3 = (const float*)d_in[3];
    const float* g1 = (const float*)d_in[4];
    const float* b1 = (const float*)d_in[5];
    const float* g2 = (const float*)d_in[6];
    const float* b2 = (const float*)d_in[7];
    float* out = (float*)d_out;

    zero_stats_kernel<<<1, 3*HID>>>();
    point_feats_kernel<<<Bsz*Npt, HID>>>(x, W1);
    dim3 kg(Npt/KNN_TQ, Bsz);
    knn_kernel<<<kg, KNN_TQ>>>(x);
    stats1_kernel<<<4096, 256>>>();
    finalize_kernel<<<1, HID>>>(0, g1, b1);
    layer_kernel<0><<<NROW/128, 256>>>(W2);
    finalize_kernel<<<1, HID>>>(1, g1, b1);
    layer_kernel<1><<<NROW/128, 256>>>(W3);
    finalize_kernel<<<1, HID>>>(2, g2, b2);
    final_kernel<<<Bsz*Npt/64, 256>>>(out);
}

// round 3
// speedup vs baseline: 4.9778x; 1.0546x over previous
#include <cuda_runtime.h>

#define Bsz 16
#define Npt 4096
#define Kn  20
#define NROW (Bsz*Npt*Kn)      // 1,310,720 rows
#define HID 64
#define NEG_SLOPE 0.2f
#define EPSBN 1e-5f
#define NBLK (NROW/128)        // 10240 layer blocks

// ---------------- scratch (device globals; no runtime allocation) ----------------
__device__ int   g_idx[Bsz*Npt*Kn];                 // kNN index sets (local to batch)
__device__ float g_A  [Bsz*Npt*HID];                // x . W1a^T  (gathered by neighbor)
__device__ float g_Bv [Bsz*Npt*HID];                // x . (W1b-W1a)^T (per center point)
__device__ float g_z2 [(size_t)NROW*HID];           // lrelu(layer2) rows
__device__ float g_pm [(size_t)NBLK*8*HID];         // per-block partial maxes of lrelu(z3)
__device__ float g_sum[3][HID];
__device__ float g_sq [3][HID];
__device__ float g_scale[3][HID];
__device__ float g_shift[3][HID];

__device__ __forceinline__ float lrelu(float v){ return v > 0.f ? v : NEG_SLOPE*v; }

// ordered-int map for float max via integer atomics (monotone for all finite floats)
__device__ __forceinline__ int okey(float f){
    int i = __float_as_int(f);
    return i >= 0 ? i : (i ^ 0x7FFFFFFF);
}
__device__ __forceinline__ float ikey(int k){
    return __int_as_float(k >= 0 ? k : (k ^ 0x7FFFFFFF));
}

// packed f32x2 helpers (sm_100+)
#define FMA2(d,a,b,c) asm("fma.rn.f32x2 %0, %1, %2, %3;" : "=l"(d) : "l"(a), "l"(b), "l"(c))
__device__ __forceinline__ unsigned long long packff(float lo, float hi){
    unsigned long long r;
    asm("mov.b64 %0, {%1, %2};" : "=l"(r) : "r"(__float_as_uint(lo)), "r"(__float_as_uint(hi)));
    return r;
}
__device__ __forceinline__ void unpackff(unsigned long long a, float& lo, float& hi){
    unsigned ulo, uhi;
    asm("mov.b64 {%0, %1}, %2;" : "=r"(ulo), "=r"(uhi) : "l"(a));
    lo = __uint_as_float(ulo); hi = __uint_as_float(uhi);
}

// ---------------- init: zero stat accumulators (graph replay safe) ----------------
__global__ void zero_stats_kernel(){
    int t = threadIdx.x;
    if (t < 3*HID){ ((float*)g_sum)[t] = 0.f; ((float*)g_sq)[t] = 0.f; }
}

// ---------------- per-point precompute for linearized layer 1 ----------------
// f = [nbr-x, x]; y1 = f @ W1^T = nbr.W1a^T + x.(W1b-W1a)^T  => A[nbr] + Bv[n]
__global__ void point_feats_kernel(const float* __restrict__ x, const float* __restrict__ W1){
    int p = blockIdx.x;            // global point 0..65535
    int o = threadIdx.x;           // channel 0..63
    int b = p >> 12, n = p & (Npt-1);
    const float* xb = x + (size_t)b*3*Npt;
    float x0 = __ldg(xb + n), x1 = __ldg(xb + Npt + n), x2 = __ldg(xb + 2*Npt + n);
    float w0 = W1[o*6+0], w1 = W1[o*6+1], w2 = W1[o*6+2];
    float w3 = W1[o*6+3], w4 = W1[o*6+4], w5 = W1[o*6+5];
    g_A [p*HID+o] = x0*w0 + x1*w1 + x2*w2;
    g_Bv[p*HID+o] = x0*(w3-w0) + x1*(w4-w1) + x2*(w5-w2);
}

// ---------------- exact kNN, two-phase threshold select, pure registers ----------------
#define KNN_TQ   128
#define KNN_TILE 1024

__device__ __forceinline__ float pair_v(float xi0,float xi1,float xi2,float sqi,float4 p){
    float dot = __fmaf_rn(xi2, p.z, __fmaf_rn(xi1, p.y, __fmul_rn(xi0, p.x)));
    return __fsub_rn(__fsub_rn(__fmul_rn(2.f, dot), sqi), p.w);
}

__device__ __forceinline__ void bubble20(float (&kv)[Kn], float v){
    float c = v;
    #pragma unroll
    for (int t = 0; t < Kn-1; t++){
        float lo = fminf(kv[t+1], c);
        float hi = fmaxf(kv[t+1], c);
        kv[t] = lo; c = hi;
    }
    kv[Kn-1] = c;
}

__global__ void __launch_bounds__(KNN_TQ) knn_kernel(const float* __restrict__ x){
    __shared__ float4 tile[KNN_TILE];
    int b = blockIdx.y;
    int i = blockIdx.x*KNN_TQ + threadIdx.x;
    const float* xb = x + (size_t)b*3*Npt;
    float xi0 = xb[i], xi1 = xb[Npt+i], xi2 = xb[2*Npt+i];
    float sqi = __fmaf_rn(xi2, xi2, __fmaf_rn(xi1, xi1, __fmul_rn(xi0, xi0)));

    const float NEG_INF = -__int_as_float(0x7f800000);
    float kv[Kn];                                  // ascending; kv[0] = 20th largest
    #pragma unroll
    for (int t = 0; t < Kn; t++) kv[t] = NEG_INF;

    // ---- phase 1: values (4-wide grouped guard; same multiset as sequential) ----
    for (int t0 = 0; t0 < Npt; t0 += KNN_TILE){
        __syncthreads();
        for (int j = threadIdx.x; j < KNN_TILE; j += KNN_TQ){
            float px = xb[t0+j], py = xb[Npt+t0+j], pz = xb[2*Npt+t0+j];
            tile[j] = make_float4(px, py, pz,
                __fmaf_rn(pz, pz, __fmaf_rn(py, py, __fmul_rn(px, px))));
        }
        __syncthreads();
        for (int j = 0; j < KNN_TILE; j += 4){
            float4 p0 = tile[j+0], p1 = tile[j+1], p2 = tile[j+2], p3 = tile[j+3];
            float v0 = pair_v(xi0, xi1, xi2, sqi, p0);
            float v1 = pair_v(xi0, xi1, xi2, sqi, p1);
            float v2 = pair_v(xi0, xi1, xi2, sqi, p2);
            float v3 = pair_v(xi0, xi1, xi2, sqi, p3);
            float m = fmaxf(fmaxf(v0, v1), fmaxf(v2, v3));
            if (m > kv[0]){
                if (v0 > kv[0]) bubble20(kv, v0);
                if (v1 > kv[0]) bubble20(kv, v1);
                if (v2 > kv[0]) bubble20(kv, v2);
                if (v3 > kv[0]) bubble20(kv, v3);
            }
        }
    }

    float T = kv[0];
    int e = 0;
    #pragma unroll
    for (int t = 0; t < Kn; t++) e += (kv[t] == T) ? 1 : 0;

    // ---- phase 2: indices (ascending j; ties at T take lowest indices) ----
    int base = (b*Npt + i)*Kn;
    int cnt = 0;
    for (int t0 = 0; t0 < Npt; t0 += KNN_TILE){
        __syncthreads();
        for (int j = threadIdx.x; j < KNN_TILE; j += KNN_TQ){
            float px = xb[t0+j], py = xb[Npt+t0+j], pz = xb[2*Npt+t0+j];
            tile[j] = make_float4(px, py, pz,
                __fmaf_rn(pz, pz, __fmaf_rn(py, py, __fmul_rn(px, px))));
        }
        __syncthreads();
        for (int j = 0; j < KNN_TILE; j += 4){
            float4 p0 = tile[j+0], p1 = tile[j+1], p2 = tile[j+2], p3 = tile[j+3];
            float v0 = pair_v(xi0, xi1, xi2, sqi, p0);
            float v1 = pair_v(xi0, xi1, xi2, sqi, p1);
            float v2 = pair_v(xi0, xi1, xi2, sqi, p2);
            float v3 = pair_v(xi0, xi1, xi2, sqi, p3);
            float m = fmaxf(fmaxf(v0, v1), fmaxf(v2, v3));
            if (m >= T && cnt < Kn){
                float vv[4] = {v0, v1, v2, v3};
                #pragma unroll
                for (int u = 0; u < 4; u++){
                    float v = vv[u];
                    if (v >= T && cnt < Kn){
                        if (v > T){
                            g_idx[base + cnt++] = t0 + j + u;
                        } else if (e > 0){
                            g_idx[base + cnt++] = t0 + j + u;
                            e--;
                        }
                    }
                }
            }
        }
    }
    for (; cnt < Kn; cnt++) g_idx[base + cnt] = i;  // safety (unreachable)
}

// ---------------- stats of z1 = lrelu(A[nbr]+Bv[n]), point-major (Bv read once) ----------------
// thread = (point, quarter): 16 channels; 2 points per thread (512 blocks x 256 thr)
__global__ void __launch_bounds__(256) stats1_kernel(){
    int t  = blockIdx.x*256 + threadIdx.x;
    int qo = (t & 3)*16;                      // channel offset
    int pbase = t >> 2;                       // 0..32767

    float s[16], qq[16];
    #pragma unroll
    for (int u = 0; u < 16; u++){ s[u] = 0.f; qq[u] = 0.f; }

    #pragma unroll
    for (int half = 0; half < 2; half++){
        int p = pbase + half*32768;
        int b = p >> 12;
        const float4* Bp = (const float4*)(g_Bv + (size_t)p*HID + qo);
        float4 B0 = Bp[0], B1 = Bp[1], B2 = Bp[2], B3 = Bp[3];
        float bv[16] = {B0.x,B0.y,B0.z,B0.w, B1.x,B1.y,B1.z,B1.w,
                        B2.x,B2.y,B2.z,B2.w, B3.x,B3.y,B3.z,B3.w};
        int ib = p*Kn;
        for (int k = 0; k < Kn; k++){
            int nbr = g_idx[ib + k];
            const float4* Ap = (const float4*)(g_A + (size_t)((b<<12)+nbr)*HID + qo);
            float4 A0 = Ap[0], A1 = Ap[1], A2 = Ap[2], A3 = Ap[3];
            float av[16] = {A0.x,A0.y,A0.z,A0.w, A1.x,A1.y,A1.z,A1.w,
                            A2.x,A2.y,A2.z,A2.w, A3.x,A3.y,A3.z,A3.w};
            #pragma unroll
            for (int u = 0; u < 16; u++){
                float z = lrelu(av[u] + bv[u]);
                s[u] += z; qq[u] += z*z;
            }
        }
    }

    __shared__ float shs[HID], shq[HID];
    if (threadIdx.x < HID){ shs[threadIdx.x] = 0.f; shq[threadIdx.x] = 0.f; }
    __syncthreads();
    #pragma unroll
    for (int u = 0; u < 16; u++){
        atomicAdd(&shs[qo+u], s[u]);
        atomicAdd(&shq[qo+u], qq[u]);
    }
    __syncthreads();
    if (threadIdx.x < HID){
        atomicAdd(&g_sum[0][threadIdx.x], shs[threadIdx.x]);
        atomicAdd(&g_sq [0][threadIdx.x], shq[threadIdx.x]);
    }
}

// ---------------- BN affine finalize: z -> z*scale + shift ----------------
__global__ void finalize_kernel(int l, const float* __restrict__ gam, const float* __restrict__ bet){
    int c = threadIdx.x;
    float inv = 1.f/(float)NROW;
    float mu  = g_sum[l][c]*inv;
    float var = g_sq[l][c]*inv - mu*mu;
    float sc  = gam[c]*rsqrtf(var + EPSBN);
    g_scale[l][c] = sc;
    g_shift[l][c] = bet[c] - mu*sc;
}

// ---------------- fused normalize + 64x64 GEMM (f32x2) + lrelu + stats (+max) ----------------
// MODE 0: input = recomputed z1 (gather A/Bv), weights W2, writes g_z2, stats slot 1
// MODE 1: input = g_z2, weights W3, stats slot 2, per-block partial max -> g_pm (z3 never stored)
template<int MODE>
__global__ void __launch_bounds__(256) layer_kernel(const float* __restrict__ W){
    __shared__ __align__(16) float ws [HID][HID];   // ws[c][o] = W[o][c]
    __shared__ __align__(16) float ins[HID][128];   // ins[c][row_local] (normalized input)
    __shared__ int spm[8][65];                      // ordered-key maxes per (slot, channel)
    int tid = threadIdx.x;
    int row0 = blockIdx.x * 128;

    for (int t = tid; t < HID*HID; t += 256)
        ws[t & 63][t >> 6] = W[t];

    {   // load + normalize 128 rows x 64 ch; 2 threads/row (32-channel halves)
        int lr = tid >> 1, h = (tid & 1)*32;
        int row = row0 + lr;
        if (MODE == 0){
            int pnt = row / Kn;
            int b = pnt >> 12;
            int nbr = g_idx[row];
            const float4* P0 = (const float4*)(g_A  + (size_t)((b<<12)+nbr)*HID + h);
            const float4* P1 = (const float4*)(g_Bv + (size_t)pnt*HID + h);
            #pragma unroll
            for (int u = 0; u < 8; u++){
                float4 a = P0[u], v = P1[u];
                int c = h + u*4;
                ins[c+0][lr] = lrelu(a.x+v.x)*g_scale[0][c+0] + g_shift[0][c+0];
                ins[c+1][lr] = lrelu(a.y+v.y)*g_scale[0][c+1] + g_shift[0][c+1];
                ins[c+2][lr] = lrelu(a.z+v.z)*g_scale[0][c+2] + g_shift[0][c+2];
                ins[c+3][lr] = lrelu(a.w+v.w)*g_scale[0][c+3] + g_shift[0][c+3];
            }
        } else {
            const float4* Z = (const float4*)(g_z2 + (size_t)row*HID + h);
            #pragma unroll
            for (int u = 0; u < 8; u++){
                float4 zz = Z[u];
                int c = h + u*4;
                ins[c+0][lr] = zz.x*g_scale[1][c+0] + g_shift[1][c+0];
                ins[c+1][lr] = zz.y*g_scale[1][c+1] + g_shift[1][c+1];
                ins[c+2][lr] = zz.z*g_scale[1][c+2] + g_shift[1][c+2];
                ins[c+3][lr] = zz.w*g_scale[1][c+3] + g_shift[1][c+3];
            }
        }
    }
    __syncthreads();

    int tr = tid >> 4;           // 16 row groups of 8
    int tc = (tid & 15)*4;       // 16 col groups of 4

    unsigned long long acc[4][4];
    #pragma unroll
    for (int rp = 0; rp < 4; rp++)
        #pragma unroll
        for (int j = 0; j < 4; j++) acc[rp][j] = 0ULL;

    #pragma unroll 8
    for (int c = 0; c < HID; c++){
        float4 w4 = *(const float4*)&ws[c][tc];
        ulonglong2 I0 = *(const ulonglong2*)&ins[c][tr*8];
        ulonglong2 I1 = *(const ulonglong2*)&ins[c][tr*8+4];
        unsigned long long inp[4] = {I0.x, I0.y, I1.x, I1.y};
        unsigned long long ww [4] = {packff(w4.x,w4.x), packff(w4.y,w4.y),
                                     packff(w4.z,w4.z), packff(w4.w,w4.w)};
        #pragma unroll
        for (int rp = 0; rp < 4; rp++)
            #pragma unroll
            for (int j = 0; j < 4; j++)
                FMA2(acc[rp][j], inp[rp], ww[j], acc[rp][j]);
    }
    __syncthreads();

    // reuse ins smem for block stat reduction; init spm for MODE 1
    float* shs = &ins[0][0];
    float* shq = shs + HID;
    if (tid < 2*HID) shs[tid] = 0.f;
    if (MODE == 1){
        for (int u = tid; u < 8*65; u += 256) ((int*)spm)[u] = 0x80000000;
    }
    __syncthreads();

    const float NEG_INF = -__int_as_float(0x7f800000);
    int slotbase = row0 / Kn;
    int sA = (row0 + tr*8) / Kn - slotbase;         // slot of this thread's first row
    float amax[4] = {NEG_INF,NEG_INF,NEG_INF,NEG_INF};
    float bmax[4] = {NEG_INF,NEG_INF,NEG_INF,NEG_INF};

    float ls[4] = {0,0,0,0}, lq[4] = {0,0,0,0};
    #pragma unroll
    for (int rp = 0; rp < 4; rp++){
        float zlo[4], zhi[4];
        #pragma unroll
        for (int j = 0; j < 4; j++){
            float lo, hi; unpackff(acc[rp][j], lo, hi);
            zlo[j] = lrelu(lo); zhi[j] = lrelu(hi);
            ls[j] += zlo[j] + zhi[j];
            lq[j] += zlo[j]*zlo[j] + zhi[j]*zhi[j];
        }
        int rlo = row0 + tr*8 + 2*rp;
        if (MODE == 0){
            *(float4*)(g_z2 + (size_t)rlo*HID + tc)     = make_float4(zlo[0],zlo[1],zlo[2],zlo[3]);
            *(float4*)(g_z2 + (size_t)(rlo+1)*HID + tc) = make_float4(zhi[0],zhi[1],zhi[2],zhi[3]);
        } else {
            bool lo_inA = (rlo    / Kn - slotbase) == sA;
            bool hi_inA = ((rlo+1)/ Kn - slotbase) == sA;
            #pragma unroll
            for (int j = 0; j < 4; j++){
                amax[j] = lo_inA ? fmaxf(amax[j], zlo[j]) : amax[j];
                bmax[j] = lo_inA ? bmax[j] : fmaxf(bmax[j], zlo[j]);
                amax[j] = hi_inA ? fmaxf(amax[j], zhi[j]) : amax[j];
                bmax[j] = hi_inA ? bmax[j] : fmaxf(bmax[j], zhi[j]);
            }
        }
    }
    if (MODE == 1){
        int sB = sA + 1;
        #pragma unroll
        for (int j = 0; j < 4; j++){
            atomicMax(&spm[sA][tc+j], okey(amax[j]));
            if (sB < 8) atomicMax(&spm[sB][tc+j], okey(bmax[j]));
        }
    }
    #pragma unroll
    for (int j = 0; j < 4; j++){
        atomicAdd(&shs[tc+j], ls[j]);
        atomicAdd(&shq[tc+j], lq[j]);
    }
    __syncthreads();
    if (tid < HID){
        atomicAdd(&g_sum[MODE+1][tid], shs[tid]);
        atomicAdd(&g_sq [MODE+1][tid], shq[tid]);
    }
    if (MODE == 1){
        for (int u = tid; u < 8*HID; u += 256)
            g_pm[(size_t)blockIdx.x*(8*HID) + u] = ikey(spm[u>>6][u&63]);
    }
}

// ---------------- combine partial maxes, BN3 affine (monotone), transpose to [B,64,N] ----------------
__global__ void __launch_bounds__(256) final_kernel(float* __restrict__ out){
    __shared__ float sh[HID][65];
    int pt0 = blockIdx.x * 64;                     // 64 points per block
    int ch = threadIdx.x & 63;
    float sc = g_scale[2][ch], tt = g_shift[2][ch];
    for (int pl = threadIdx.x >> 6; pl < 64; pl += 4){
        int p = pt0 + pl;
        int r0 = p*Kn, r1 = r0 + Kn - 1;
        int b0 = r0 >> 7, b1 = r1 >> 7;
        int s0 = p - (b0 << 7)/Kn;
        float m = g_pm[(size_t)b0*(8*HID) + s0*HID + ch];
        if (b1 != b0){
            int s1 = p - (b1 << 7)/Kn;
            m = fmaxf(m, g_pm[(size_t)b1*(8*HID) + s1*HID + ch]);
        }
        sh[ch][pl] = m*sc + tt;
    }
    __syncthreads();
    int b = pt0 >> 12, n0 = pt0 & (Npt-1);
    int n = threadIdx.x & 63;
    for (int ol = threadIdx.x >> 6; ol < 64; ol += 4)
        out[((size_t)b*HID + ol)*Npt + n0 + n] = sh[ol][n];
}

// ---------------- launch ----------------
extern "C" void kernel_launch(void* const* d_in, const int* in_sizes, int n_in,
                              void* d_out, int out_size){
    const float* x  = (const float*)d_in[0];
    const float* W1 = (const float*)d_in[1];
    const float* W2 = (const float*)d_in[2];
    const float* W3 = (const float*)d_in[3];
    const float* g1 = (const float*)d_in[4];
    const float* b1 = (const float*)d_in[5];
    const float* g2 = (const float*)d_in[6];
    const float* b2 = (const float*)d_in[7];
    float* out = (float*)d_out;

    zero_stats_kernel<<<1, 3*HID>>>();
    point_feats_kernel<<<Bsz*Npt, HID>>>(x, W1);
    dim3 kg(Npt/KNN_TQ, Bsz);
    knn_kernel<<<kg, KNN_TQ>>>(x);
    stats1_kernel<<<512, 256>>>();
    finalize_kernel<<<1, HID>>>(0, g1, b1);
    layer_kernel<0><<<NBLK, 256>>>(W2);
    finalize_kernel<<<1, HID>>>(1, g1, b1);
    layer_kernel<1><<<NBLK, 256>>>(W3);
    finalize_kernel<<<1, HID>>>(2, g2, b2);
    final_kernel<<<Bsz*Npt/64, 256>>>(out);
}

// round 4
// speedup vs baseline: 5.3910x; 1.0830x over previous
#include <cuda_runtime.h>

#define Bsz 16
#define Npt 4096
#define Kn  20
#define NROW (Bsz*Npt*Kn)      // 1,310,720 rows
#define HID 64
#define NEG_SLOPE 0.2f
#define EPSBN 1e-5f
#define NBLK (NROW/128)        // 10240 layer blocks

// ---------------- scratch (device globals; no runtime allocation) ----------------
__device__ int   g_idx[Bsz*Npt*Kn];                 // kNN index sets (local to batch)
__device__ float g_A  [Bsz*Npt*HID];                // x . W1a^T  (gathered by neighbor)
__device__ float g_Bv [Bsz*Npt*HID];                // x . (W1b-W1a)^T (per center point)
__device__ float g_z2 [(size_t)NROW*HID];           // lrelu(layer2) rows
__device__ float g_pm [(size_t)NBLK*8*HID];         // per-block partial maxes of lrelu(z3)
__device__ float g_sum[3][HID];
__device__ float g_sq [3][HID];
__device__ float g_scale[3][HID];
__device__ float g_shift[3][HID];

__device__ __forceinline__ float lrelu(float v){ return v > 0.f ? v : NEG_SLOPE*v; }

// ordered-int map for float max via integer atomics (monotone for all finite floats)
__device__ __forceinline__ int okey(float f){
    int i = __float_as_int(f);
    return i >= 0 ? i : (i ^ 0x7FFFFFFF);
}
__device__ __forceinline__ float ikey(int k){
    return __int_as_float(k >= 0 ? k : (k ^ 0x7FFFFFFF));
}

// packed f32x2 helpers (sm_100+)
#define FMA2(d,a,b,c) asm("fma.rn.f32x2 %0, %1, %2, %3;" : "=l"(d) : "l"(a), "l"(b), "l"(c))
__device__ __forceinline__ unsigned long long packff(float lo, float hi){
    unsigned long long r;
    asm("mov.b64 %0, {%1, %2};" : "=l"(r) : "r"(__float_as_uint(lo)), "r"(__float_as_uint(hi)));
    return r;
}
__device__ __forceinline__ void unpackff(unsigned long long a, float& lo, float& hi){
    unsigned ulo, uhi;
    asm("mov.b64 {%0, %1}, %2;" : "=r"(ulo), "=r"(uhi) : "l"(a));
    lo = __uint_as_float(ulo); hi = __uint_as_float(uhi);
}

// ---------------- init: zero stat accumulators (graph replay safe) ----------------
__global__ void zero_stats_kernel(){
    int t = threadIdx.x;
    if (t < 3*HID){ ((float*)g_sum)[t] = 0.f; ((float*)g_sq)[t] = 0.f; }
}

// ---------------- per-point precompute for linearized layer 1 ----------------
// f = [nbr-x, x]; y1 = f @ W1^T = nbr.W1a^T + x.(W1b-W1a)^T  => A[nbr] + Bv[n]
__global__ void point_feats_kernel(const float* __restrict__ x, const float* __restrict__ W1){
    int p = blockIdx.x;            // global point 0..65535
    int o = threadIdx.x;           // channel 0..63
    int b = p >> 12, n = p & (Npt-1);
    const float* xb = x + (size_t)b*3*Npt;
    float x0 = __ldg(xb + n), x1 = __ldg(xb + Npt + n), x2 = __ldg(xb + 2*Npt + n);
    float w0 = W1[o*6+0], w1 = W1[o*6+1], w2 = W1[o*6+2];
    float w3 = W1[o*6+3], w4 = W1[o*6+4], w5 = W1[o*6+5];
    g_A [p*HID+o] = x0*w0 + x1*w1 + x2*w2;
    g_Bv[p*HID+o] = x0*(w3-w0) + x1*(w4-w1) + x2*(w5-w2);
}

// ---------------- exact kNN: warp-cooperative top-20, u64 keys, divergence-free ----------------
// key = (okey(v)^signflip)<<32 | (4095-j): ordering = v desc, then j asc == jax top_k ties.
// Sorted top-20 lives across lanes 0..19 (one key per lane). Insertion = ballot+shfl shift,
// fully warp-uniform. Single pass; index recovered from key low bits.
#define KNN_CHUNK 2048

__device__ __forceinline__ float pair_v(float xi0,float xi1,float xi2,float sqi,float4 p){
    float dot = __fmaf_rn(xi2, p.z, __fmaf_rn(xi1, p.y, __fmul_rn(xi0, p.x)));
    return __fsub_rn(__fsub_rn(__fmul_rn(2.f, dot), sqi), p.w);
}

__global__ void __launch_bounds__(256) knn_kernel(const float* __restrict__ x){
    __shared__ float4 pts[KNN_CHUNK];               // 32KB
    const unsigned FULL = 0xFFFFFFFFu;
    int b     = blockIdx.x >> 9;                    // 512 blocks per batch
    int qbase = (blockIdx.x & 511)*8;               // 8 queries (warps) per block
    int wid  = threadIdx.x >> 5;
    int lane = threadIdx.x & 31;
    const float* xb = x + (size_t)b*3*Npt;

    int q = qbase + wid;
    float xi0 = xb[q], xi1 = xb[Npt+q], xi2 = xb[2*Npt+q];
    float sqi = __fmaf_rn(xi2, xi2, __fmaf_rn(xi1, xi1, __fmul_rn(xi0, xi0)));

    unsigned long long key = 0ULL;                  // lanes 0..19: sorted desc; 0 < any real key
    unsigned long long thr = 0ULL;                  // current 20th key (lane19), warp-uniform

    for (int c0 = 0; c0 < Npt; c0 += KNN_CHUNK){
        __syncthreads();
        for (int t = threadIdx.x; t < KNN_CHUNK; t += 256){
            float px = xb[c0+t], py = xb[Npt+c0+t], pz = xb[2*Npt+c0+t];
            pts[t] = make_float4(px, py, pz,
                __fmaf_rn(pz, pz, __fmaf_rn(py, py, __fmul_rn(px, px))));
        }
        __syncthreads();

        for (int j0 = 0; j0 < KNN_CHUNK; j0 += 32){
            int j = c0 + j0 + lane;
            float v = pair_v(xi0, xi1, xi2, sqi, pts[j0 + lane]);
            unsigned hi = (unsigned)okey(v) ^ 0x80000000u;
            unsigned long long cand = ((unsigned long long)hi << 32) | (unsigned)(Npt-1-j);
            unsigned mask = __ballot_sync(FULL, cand > thr);
            while (mask){
                int src = __ffs(mask) - 1; mask &= mask - 1;
                unsigned long long kn = __shfl_sync(FULL, cand, src);
                unsigned gt = __ballot_sync(FULL, key > kn) & 0xFFFFFu;   // kept lanes above kn
                int pos = __popc(gt);                                      // insertion slot
                unsigned long long up = __shfl_up_sync(FULL, key, 1);
                if (lane < Kn){
                    if (lane == pos) key = kn;
                    else if (lane > pos) key = up;
                }
                thr = __shfl_sync(FULL, key, Kn-1);
            }
        }
    }
    if (lane < Kn){
        int idx = (Npt-1) - (int)(key & 0xFFFFFFFFull);
        g_idx[(b*Npt + q)*Kn + lane] = idx;
    }
}

// ---------------- stats of z1 = lrelu(A[nbr]+Bv[n]), point-major (Bv read once) ----------------
// thread = (point, quarter): 16 channels; 1 point per thread (1024 blocks x 256 thr)
__global__ void __launch_bounds__(256) stats1_kernel(){
    int t  = blockIdx.x*256 + threadIdx.x;
    int qo = (t & 3)*16;                      // channel offset
    int p  = t >> 2;                          // 0..65535

    float s[16], qq[16];
    #pragma unroll
    for (int u = 0; u < 16; u++){ s[u] = 0.f; qq[u] = 0.f; }

    int b = p >> 12;
    const float4* Bp = (const float4*)(g_Bv + (size_t)p*HID + qo);
    float4 B0 = Bp[0], B1 = Bp[1], B2 = Bp[2], B3 = Bp[3];
    float bv[16] = {B0.x,B0.y,B0.z,B0.w, B1.x,B1.y,B1.z,B1.w,
                    B2.x,B2.y,B2.z,B2.w, B3.x,B3.y,B3.z,B3.w};
    int ib = p*Kn;
    for (int k = 0; k < Kn; k++){
        int nbr = g_idx[ib + k];
        const float4* Ap = (const float4*)(g_A + (size_t)((b<<12)+nbr)*HID + qo);
        float4 A0 = Ap[0], A1 = Ap[1], A2 = Ap[2], A3 = Ap[3];
        float av[16] = {A0.x,A0.y,A0.z,A0.w, A1.x,A1.y,A1.z,A1.w,
                        A2.x,A2.y,A2.z,A2.w, A3.x,A3.y,A3.z,A3.w};
        #pragma unroll
        for (int u = 0; u < 16; u++){
            float z = lrelu(av[u] + bv[u]);
            s[u] += z; qq[u] += z*z;
        }
    }

    __shared__ float shs[HID], shq[HID];
    if (threadIdx.x < HID){ shs[threadIdx.x] = 0.f; shq[threadIdx.x] = 0.f; }
    __syncthreads();
    #pragma unroll
    for (int u = 0; u < 16; u++){
        atomicAdd(&shs[qo+u], s[u]);
        atomicAdd(&shq[qo+u], qq[u]);
    }
    __syncthreads();
    if (threadIdx.x < HID){
        atomicAdd(&g_sum[0][threadIdx.x], shs[threadIdx.x]);
        atomicAdd(&g_sq [0][threadIdx.x], shq[threadIdx.x]);
    }
}

// ---------------- BN affine finalize: z -> z*scale + shift ----------------
__global__ void finalize_kernel(int l, const float* __restrict__ gam, const float* __restrict__ bet){
    int c = threadIdx.x;
    float inv = 1.f/(float)NROW;
    float mu  = g_sum[l][c]*inv;
    float var = g_sq[l][c]*inv - mu*mu;
    float sc  = gam[c]*rsqrtf(var + EPSBN);
    g_scale[l][c] = sc;
    g_shift[l][c] = bet[c] - mu*sc;
}

// ---------------- fused normalize + 64x64 GEMM (f32x2) + lrelu + stats (+max) ----------------
// MODE 0: input = recomputed z1 (gather A/Bv), weights W2, writes g_z2, stats slot 1
// MODE 1: input = g_z2, weights W3, stats slot 2, per-block partial max -> g_pm (z3 never stored)
template<int MODE>
__global__ void __launch_bounds__(256) layer_kernel(const float* __restrict__ W){
    __shared__ __align__(16) float ws [HID][HID];   // ws[c][o] = W[o][c]
    __shared__ __align__(16) float ins[HID][128];   // ins[c][row_local] (normalized input)
    __shared__ int spm[8][65];                      // ordered-key maxes per (slot, channel)
    int tid = threadIdx.x;
    int row0 = blockIdx.x * 128;

    for (int t = tid; t < HID*HID; t += 256)
        ws[t & 63][t >> 6] = W[t];

    {   // load + normalize 128 rows x 64 ch; 2 threads/row (32-channel halves)
        int lr = tid >> 1, h = (tid & 1)*32;
        int row = row0 + lr;
        if (MODE == 0){
            int pnt = row / Kn;
            int b = pnt >> 12;
            int nbr = g_idx[row];
            const float4* P0 = (const float4*)(g_A  + (size_t)((b<<12)+nbr)*HID + h);
            const float4* P1 = (const float4*)(g_Bv + (size_t)pnt*HID + h);
            #pragma unroll
            for (int u = 0; u < 8; u++){
                float4 a = P0[u], v = P1[u];
                int c = h + u*4;
                ins[c+0][lr] = lrelu(a.x+v.x)*g_scale[0][c+0] + g_shift[0][c+0];
                ins[c+1][lr] = lrelu(a.y+v.y)*g_scale[0][c+1] + g_shift[0][c+1];
                ins[c+2][lr] = lrelu(a.z+v.z)*g_scale[0][c+2] + g_shift[0][c+2];
                ins[c+3][lr] = lrelu(a.w+v.w)*g_scale[0][c+3] + g_shift[0][c+3];
            }
        } else {
            const float4* Z = (const float4*)(g_z2 + (size_t)row*HID + h);
            #pragma unroll
            for (int u = 0; u < 8; u++){
                float4 zz = Z[u];
                int c = h + u*4;
                ins[c+0][lr] = zz.x*g_scale[1][c+0] + g_shift[1][c+0];
                ins[c+1][lr] = zz.y*g_scale[1][c+1] + g_shift[1][c+1];
                ins[c+2][lr] = zz.z*g_scale[1][c+2] + g_shift[1][c+2];
                ins[c+3][lr] = zz.w*g_scale[1][c+3] + g_shift[1][c+3];
            }
        }
    }
    __syncthreads();

    int tr = tid >> 4;           // 16 row groups of 8
    int tc = (tid & 15)*4;       // 16 col groups of 4

    unsigned long long acc[4][4];
    #pragma unroll
    for (int rp = 0; rp < 4; rp++)
        #pragma unroll
        for (int j = 0; j < 4; j++) acc[rp][j] = 0ULL;

    #pragma unroll 8
    for (int c = 0; c < HID; c++){
        float4 w4 = *(const float4*)&ws[c][tc];
        ulonglong2 I0 = *(const ulonglong2*)&ins[c][tr*8];
        ulonglong2 I1 = *(const ulonglong2*)&ins[c][tr*8+4];
        unsigned long long inp[4] = {I0.x, I0.y, I1.x, I1.y};
        unsigned long long ww [4] = {packff(w4.x,w4.x), packff(w4.y,w4.y),
                                     packff(w4.z,w4.z), packff(w4.w,w4.w)};
        #pragma unroll
        for (int rp = 0; rp < 4; rp++)
            #pragma unroll
            for (int j = 0; j < 4; j++)
                FMA2(acc[rp][j], inp[rp], ww[j], acc[rp][j]);
    }
    __syncthreads();

    // reuse ins smem for block stat reduction; init spm for MODE 1
    float* shs = &ins[0][0];
    float* shq = shs + HID;
    if (tid < 2*HID) shs[tid] = 0.f;
    if (MODE == 1){
        for (int u = tid; u < 8*65; u += 256) ((int*)spm)[u] = 0x80000000;
    }
    __syncthreads();

    const float NEG_INF = -__int_as_float(0x7f800000);
    int slotbase = row0 / Kn;
    int sA = (row0 + tr*8) / Kn - slotbase;         // slot of this thread's first row
    float amax[4] = {NEG_INF,NEG_INF,NEG_INF,NEG_INF};
    float bmax[4] = {NEG_INF,NEG_INF,NEG_INF,NEG_INF};

    float ls[4] = {0,0,0,0}, lq[4] = {0,0,0,0};
    #pragma unroll
    for (int rp = 0; rp < 4; rp++){
        float zlo[4], zhi[4];
        #pragma unroll
        for (int j = 0; j < 4; j++){
            float lo, hi; unpackff(acc[rp][j], lo, hi);
            zlo[j] = lrelu(lo); zhi[j] = lrelu(hi);
            ls[j] += zlo[j] + zhi[j];
            lq[j] += zlo[j]*zlo[j] + zhi[j]*zhi[j];
        }
        int rlo = row0 + tr*8 + 2*rp;
        if (MODE == 0){
            *(float4*)(g_z2 + (size_t)rlo*HID + tc)     = make_float4(zlo[0],zlo[1],zlo[2],zlo[3]);
            *(float4*)(g_z2 + (size_t)(rlo+1)*HID + tc) = make_float4(zhi[0],zhi[1],zhi[2],zhi[3]);
        } else {
            bool lo_inA = (rlo    / Kn - slotbase) == sA;
            bool hi_inA = ((rlo+1)/ Kn - slotbase) == sA;
            #pragma unroll
            for (int j = 0; j < 4; j++){
                amax[j] = lo_inA ? fmaxf(amax[j], zlo[j]) : amax[j];
                bmax[j] = lo_inA ? bmax[j] : fmaxf(bmax[j], zlo[j]);
                amax[j] = hi_inA ? fmaxf(amax[j], zhi[j]) : amax[j];
                bmax[j] = hi_inA ? bmax[j] : fmaxf(bmax[j], zhi[j]);
            }
        }
    }
    if (MODE == 1){
        int sB = sA + 1;
        #pragma unroll
        for (int j = 0; j < 4; j++){
            atomicMax(&spm[sA][tc+j], okey(amax[j]));
            if (sB < 8) atomicMax(&spm[sB][tc+j], okey(bmax[j]));
        }
    }
    #pragma unroll
    for (int j = 0; j < 4; j++){
        atomicAdd(&shs[tc+j], ls[j]);
        atomicAdd(&shq[tc+j], lq[j]);
    }
    __syncthreads();
    if (tid < HID){
        atomicAdd(&g_sum[MODE+1][tid], shs[tid]);
        atomicAdd(&g_sq [MODE+1][tid], shq[tid]);
    }
    if (MODE == 1){
        for (int u = tid; u < 8*HID; u += 256)
            g_pm[(size_t)blockIdx.x*(8*HID) + u] = ikey(spm[u>>6][u&63]);
    }
}

// ---------------- combine partial maxes, BN3 affine (monotone), transpose to [B,64,N] ----------------
__global__ void __launch_bounds__(256) final_kernel(float* __restrict__ out){
    __shared__ float sh[HID][65];
    int pt0 = blockIdx.x * 64;                     // 64 points per block
    int ch = threadIdx.x & 63;
    float sc = g_scale[2][ch], tt = g_shift[2][ch];
    for (int pl = threadIdx.x >> 6; pl < 64; pl += 4){
        int p = pt0 + pl;
        int r0 = p*Kn, r1 = r0 + Kn - 1;
        int b0 = r0 >> 7, b1 = r1 >> 7;
        int s0 = p - (b0 << 7)/Kn;
        float m = g_pm[(size_t)b0*(8*HID) + s0*HID + ch];
        if (b1 != b0){
            int s1 = p - (b1 << 7)/Kn;
            m = fmaxf(m, g_pm[(size_t)b1*(8*HID) + s1*HID + ch]);
        }
        sh[ch][pl] = m*sc + tt;
    }
    __syncthreads();
    int b = pt0 >> 12, n0 = pt0 & (Npt-1);
    int n = threadIdx.x & 63;
    for (int ol = threadIdx.x >> 6; ol < 64; ol += 4)
        out[((size_t)b*HID + ol)*Npt + n0 + n] = sh[ol][n];
}

// ---------------- launch ----------------
extern "C" void kernel_launch(void* const* d_in, const int* in_sizes, int n_in,
                              void* d_out, int out_size){
    const float* x  = (const float*)d_in[0];
    const float* W1 = (const float*)d_in[1];
    const float* W2 = (const float*)d_in[2];
    const float* W3 = (const float*)d_in[3];
    const float* g1 = (const float*)d_in[4];
    const float* b1 = (const float*)d_in[5];
    const float* g2 = (const float*)d_in[6];
    const float* b2 = (const float*)d_in[7];
    float* out = (float*)d_out;

    zero_stats_kernel<<<1, 3*HID>>>();
    point_feats_kernel<<<Bsz*Npt, HID>>>(x, W1);
    knn_kernel<<<Bsz*512, 256>>>(x);
    stats1_kernel<<<1024, 256>>>();
    finalize_kernel<<<1, HID>>>(0, g1, b1);
    layer_kernel<0><<<NBLK, 256>>>(W2);
    finalize_kernel<<<1, HID>>>(1, g1, b1);
    layer_kernel<1><<<NBLK, 256>>>(W3);
    finalize_kernel<<<1, HID>>>(2, g2, b2);
    final_kernel<<<Bsz*Npt/64, 256>>>(out);
}